// round 8
// baseline (speedup 1.0000x reference)
#include <cuda_runtime.h>
#include <cuda_fp16.h>
#include <cstdint>
#include <cstddef>

#define K_DIM  4096
#define M_ROWS 8192
#define N_DIM  4096
#define KQ_DIM 3968            // exact-fp16 integer-weight part
#define N_OUTL 128

// GEMM tiling
#define TM 256
#define TN 128
#define KC 64
#define NT (K_DIM / KC)        // 64 k-iterations
#define NQ_IT (KQ_DIM / KC)    // 62 q-part iterations
#define STAGES 4

// Stage smem layout (bytes): A 256x64 fp16 = 32K, B 128x64 fp16 = 16K
#define OFF_A 0
#define OFF_B (32 * 1024)
#define STAGE_BYTES (48 * 1024)
#define SMEM_TOTAL (STAGES * STAGE_BYTES)   // 196608

// ---------------------------------------------------------------------------
// Device-global scratch (no runtime allocation)
// ---------------------------------------------------------------------------
__device__ __half g_A [(size_t)M_ROWS * K_DIM];    // permuted x, fp16
__device__ __half g_Q [(size_t)N_DIM * KQ_DIM];    // exact fp16 int weights
__device__ __half g_FP[(size_t)N_DIM * N_OUTL];    // fp16 outlier weights

// ---------------------------------------------------------------------------
// Base-target PTX helpers
// ---------------------------------------------------------------------------
__device__ __forceinline__ uint32_t smem_to_u32(const void* p) {
    uint32_t a;
    asm("{ .reg .u64 t; cvta.to.shared.u64 t, %1; cvt.u32.u64 %0, t; }"
        : "=r"(a) : "l"(p));
    return a;
}

__device__ __forceinline__ void cpa16(uint32_t dst, const void* src) {
    asm volatile("cp.async.cg.shared.global [%0], [%1], 16;"
                 :: "r"(dst), "l"(src) : "memory");
}

__device__ __forceinline__ void ldsm4(uint32_t* r, uint32_t addr) {
    asm volatile("ldmatrix.sync.aligned.m8n8.x4.shared.b16 {%0,%1,%2,%3}, [%4];"
                 : "=r"(r[0]), "=r"(r[1]), "=r"(r[2]), "=r"(r[3]) : "r"(addr));
}

__device__ __forceinline__ void mma16816(float* c, const uint32_t* a,
                                         uint32_t b0, uint32_t b1) {
    asm volatile(
        "mma.sync.aligned.m16n8k16.row.col.f32.f16.f16.f32 "
        "{%0,%1,%2,%3}, {%4,%5,%6,%7}, {%8,%9}, {%0,%1,%2,%3};"
        : "+f"(c[0]), "+f"(c[1]), "+f"(c[2]), "+f"(c[3])
        : "r"(a[0]), "r"(a[1]), "r"(a[2]), "r"(a[3]), "r"(b0), "r"(b1));
}

// 128B-row tile, 8 granules of 16B, XOR-swizzled: any ldmatrix 8-lane phase
// covers all 32 banks. (row&7 invariant across our 16-row-strided fragments.)
__device__ __forceinline__ uint32_t tile_off(int row, int g) {
    return (uint32_t)(row * 128 + ((g ^ (row & 7)) * 16));
}

// ---------------------------------------------------------------------------
// Prep A: permute columns (xp[invp[c]] = x[c]) and convert fp32 -> fp16.
// ---------------------------------------------------------------------------
__global__ __launch_bounds__(256)
void perm_conv_A_kernel(const float* __restrict__ x,
                        const int* __restrict__ invp) {
    __shared__ float rs[K_DIM];
    const int m = blockIdx.x;
    const float* xr = x + (size_t)m * K_DIM;
    for (int j = threadIdx.x; j < K_DIM; j += 256)
        rs[invp[j]] = xr[j];                        // smem scatter
    __syncthreads();
    __half2* H = (__half2*)(g_A + (size_t)m * K_DIM);
    for (int j2 = threadIdx.x; j2 < K_DIM / 2; j2 += 256)
        H[j2] = __floats2half2_rn(rs[2 * j2], rs[2 * j2 + 1]);
}

// Merged weight prep: exact fp16 int weights, then fp16 outlier weights.
__global__ void prep_W_kernel(const float* __restrict__ qw,
                              const float* __restrict__ fw) {
    size_t idx = (size_t)blockIdx.x * 256 + threadIdx.x;   // N*(KQ+OUTL)
    const size_t nq = (size_t)N_DIM * KQ_DIM;
    if (idx < nq) g_Q[idx] = __float2half_rn(qw[idx]);
    else          g_FP[idx - nq] = __float2half_rn(fw[idx - nq]);
}

// ---------------------------------------------------------------------------
// GEMM: acc = xp[:, :3968]*q^T ; acc *= alpha[n] ; acc += outliers ; +bias.
// CTA 256x128, 256 threads / 8 warps (4m x 2n), warp tile 64x64, KC=64,
// 4-stage cp.async pipeline, fragment double-buffering, pointer-walk loader.
// ---------------------------------------------------------------------------
__global__ __launch_bounds__(256, 1)
void gemm_hmma_kernel(const float* __restrict__ alpha,
                      const float* __restrict__ bias,
                      float* __restrict__ C) {
    extern __shared__ char smem[];
    const uint32_t sbase = smem_to_u32(smem);
    const int tid = threadIdx.x;
    const int wid = tid >> 5;
    const int lid = tid & 31;
    const int wm  = wid >> 1;
    const int wn  = wid & 1;
    const int m0  = blockIdx.y * TM;
    const int n0  = blockIdx.x * TN;

    float acc[4][8][4];
    #pragma unroll
    for (int i = 0; i < 4; i++)
        #pragma unroll
        for (int j = 0; j < 8; j++)
            #pragma unroll
            for (int t = 0; t < 4; t++) acc[i][j][t] = 0.0f;

    // ---- loader state: walking pointers, constant offsets ----
    const int lrow = tid >> 3;          // 0..31
    const int lg   = tid & 7;           // 16B granule within 128B row
    const __half* pA = g_A + (size_t)(m0 + lrow) * K_DIM  + lg * 8;
    const __half* pQ = g_Q + (size_t)(n0 + lrow) * KQ_DIM + lg * 8;
    const __half* pF = g_FP + (size_t)(n0 + lrow) * N_OUTL + lg * 8;
    const uint32_t dA = sbase + OFF_A + tile_off(lrow, lg);  // +4096*p per row-group
    const uint32_t dB = sbase + OFF_B + tile_off(lrow, lg);

    // kt advances sequentially across all load_stage calls -> walk pointers.
    auto load_stage = [&](int slot, int kt) {
        const uint32_t so = (uint32_t)slot * STAGE_BYTES;
        #pragma unroll
        for (int p = 0; p < 8; p++)     // A: 256 rows (row-group stride 32)
            cpa16(dA + so + p * 4096u, pA + (size_t)p * 32 * K_DIM);
        if (kt < NQ_IT) {
            #pragma unroll
            for (int p = 0; p < 4; p++) // B: exact int weights
                cpa16(dB + so + p * 4096u, pQ + (size_t)p * 32 * KQ_DIM);
            pQ += KC;
        } else {
            const __half* f = pF + (size_t)(kt - NQ_IT) * KC;
            #pragma unroll
            for (int p = 0; p < 4; p++) // B: fp outlier weights
                cpa16(dB + so + p * 4096u, f + (size_t)p * 32 * N_OUTL);
        }
        pA += KC;
    };

    // ---- fragment addressing: row&7 identical for all fragments ----
    const int frow = lid & 15;
    const int fg   = lid >> 4;
    const uint32_t r7 = (uint32_t)(frow & 7);
    uint32_t aoff[4], boff[4];
    #pragma unroll
    for (int i = 0; i < 4; i++)
        aoff[i] = sbase + OFF_A + (uint32_t)(wm * 64 + i * 16 + frow) * 128;
    #pragma unroll
    for (int j = 0; j < 4; j++)
        boff[j] = sbase + OFF_B + (uint32_t)(wn * 64 + j * 16 + frow) * 128;

    uint32_t fa[2][4][4], fb[2][4][4];
    auto ldsm_step = [&](uint32_t so, int s, int buf) {
        const uint32_t sw = ((uint32_t)(2 * s + fg) ^ r7) << 4;  // shared by all 8
        #pragma unroll
        for (int j = 0; j < 4; j++) ldsm4(fb[buf][j], boff[j] + so + sw);
        #pragma unroll
        for (int i = 0; i < 4; i++) ldsm4(fa[buf][i], aoff[i] + so + sw);
    };

    const int tq = lid & 3;

    // ---- pipeline ----
    #pragma unroll
    for (int s = 0; s < STAGES - 1; s++) {
        load_stage(s, s);
        asm volatile("cp.async.commit_group;" ::: "memory");
    }
    for (int kt = 0; kt < NT; kt++) {
        asm volatile("cp.async.wait_group 2;" ::: "memory");
        __syncthreads();
        const uint32_t so = (uint32_t)(kt & (STAGES - 1)) * STAGE_BYTES;

        // kick off s=0 fragment loads first (data is ready; hide LDS latency
        // under the loader burst + first MMAs)
        ldsm_step(so, 0, 0);

        if (kt == NQ_IT) {
            // q-part complete: per-output-column alpha on accumulators
            #pragma unroll
            for (int j2 = 0; j2 < 8; j2++) {
                const int nc = n0 + wn * 64 + j2 * 8 + 2 * tq;
                const float s0 = alpha[nc], s1 = alpha[nc + 1];
                #pragma unroll
                for (int i = 0; i < 4; i++) {
                    acc[i][j2][0] *= s0; acc[i][j2][1] *= s1;
                    acc[i][j2][2] *= s0; acc[i][j2][3] *= s1;
                }
            }
        }

        const int nx = kt + STAGES - 1;
        if (nx < NT) load_stage(nx & (STAGES - 1), nx);
        asm volatile("cp.async.commit_group;" ::: "memory");

        // 4 s-steps, double-buffered fragments
        #pragma unroll
        for (int s = 0; s < 4; s++) {
            if (s < 3) ldsm_step(so, s + 1, (s + 1) & 1);
            const int b = s & 1;
            #pragma unroll
            for (int i = 0; i < 4; i++)
                #pragma unroll
                for (int j = 0; j < 4; j++) {
                    mma16816(acc[i][2 * j],     fa[b][i], fb[b][j][0], fb[b][j][2]);
                    mma16816(acc[i][2 * j + 1], fa[b][i], fb[b][j][1], fb[b][j][3]);
                }
        }
    }

    // ---- epilogue: bias + float2 stores ----
    const int qid = lid >> 2;
    #pragma unroll
    for (int i = 0; i < 4; i++) {
        const int mrow = m0 + wm * 64 + i * 16 + qid;
        #pragma unroll
        for (int j2 = 0; j2 < 8; j2++) {
            const int nc = n0 + wn * 64 + j2 * 8 + 2 * tq;
            const float b0 = bias[nc], b1 = bias[nc + 1];
            float2 v0 = make_float2(acc[i][j2][0] + b0, acc[i][j2][1] + b1);
            float2 v1 = make_float2(acc[i][j2][2] + b0, acc[i][j2][3] + b1);
            *(float2*)&C[(size_t)mrow * N_DIM + nc]       = v0;
            *(float2*)&C[(size_t)(mrow + 8) * N_DIM + nc] = v1;
        }
    }
}

// ---------------------------------------------------------------------------
// Launch. Inputs: input, q_weight, fp_weight, alpha_scale, bias, inv_col_perm.
// ---------------------------------------------------------------------------
extern "C" void kernel_launch(void* const* d_in, const int* in_sizes, int n_in,
                              void* d_out, int out_size) {
    const float* input = (const float*)d_in[0];
    const float* qw    = (const float*)d_in[1];
    const float* fw    = (const float*)d_in[2];
    const float* alpha = (const float*)d_in[3];
    const float* bias  = (const float*)d_in[4];
    const int*   invp  = (const int*)  d_in[5];
    float* out = (float*)d_out;

    perm_conv_A_kernel<<<M_ROWS, 256>>>(input, invp);
    prep_W_kernel<<<(N_DIM * K_DIM) / 256, 256>>>(qw, fw);

    static bool attr_set = false;
    if (!attr_set) {
        cudaFuncSetAttribute(gemm_hmma_kernel,
                             cudaFuncAttributeMaxDynamicSharedMemorySize, SMEM_TOTAL);
        attr_set = true;
    }
    dim3 grid(N_DIM / TN, M_ROWS / TM);   // (32, 32)
    gemm_hmma_kernel<<<grid, 256, SMEM_TOTAL>>>(alpha, bias, out);
}

// round 9
// speedup vs baseline: 1.0980x; 1.0980x over previous
#include <cuda_runtime.h>
#include <cuda_fp16.h>
#include <cstdint>
#include <cstddef>

#define K_DIM  4096
#define M_ROWS 8192
#define N_DIM  4096
#define KQ_DIM 3968            // exact-fp16 integer-weight part
#define N_OUTL 128

// GEMM tiling
#define TM 256
#define TN 128
#define KC 64
#define NT (K_DIM / KC)        // 64 k-iterations
#define NQ_IT (KQ_DIM / KC)    // 62 q-part iterations
#define STAGES 4

// Stage smem layout (bytes): A 256x64 fp16 = 32K, B 128x64 fp16 = 16K
#define OFF_A 0
#define OFF_B (32 * 1024)
#define STAGE_BYTES (48 * 1024)
#define SMEM_TOTAL (STAGES * STAGE_BYTES)   // 196608

// rows per CTA in the A-permute kernel
#define PERM_R 16

// ---------------------------------------------------------------------------
// Device-global scratch (no runtime allocation)
// ---------------------------------------------------------------------------
__device__ __half g_A [(size_t)M_ROWS * K_DIM];    // permuted x, fp16
__device__ __half g_Q [(size_t)N_DIM * KQ_DIM];    // exact fp16 int weights
__device__ __half g_FP[(size_t)N_DIM * N_OUTL];    // fp16 outlier weights

// ---------------------------------------------------------------------------
// Base-target PTX helpers
// ---------------------------------------------------------------------------
__device__ __forceinline__ uint32_t smem_to_u32(const void* p) {
    uint32_t a;
    asm("{ .reg .u64 t; cvta.to.shared.u64 t, %1; cvt.u32.u64 %0, t; }"
        : "=r"(a) : "l"(p));
    return a;
}

__device__ __forceinline__ void cpa16(uint32_t dst, const void* src) {
    asm volatile("cp.async.cg.shared.global [%0], [%1], 16;"
                 :: "r"(dst), "l"(src) : "memory");
}

__device__ __forceinline__ void ldsm4(uint32_t* r, uint32_t addr) {
    asm volatile("ldmatrix.sync.aligned.m8n8.x4.shared.b16 {%0,%1,%2,%3}, [%4];"
                 : "=r"(r[0]), "=r"(r[1]), "=r"(r[2]), "=r"(r[3]) : "r"(addr));
}

__device__ __forceinline__ void mma16816(float* c, const uint32_t* a,
                                         uint32_t b0, uint32_t b1) {
    asm volatile(
        "mma.sync.aligned.m16n8k16.row.col.f32.f16.f16.f32 "
        "{%0,%1,%2,%3}, {%4,%5,%6,%7}, {%8,%9}, {%0,%1,%2,%3};"
        : "+f"(c[0]), "+f"(c[1]), "+f"(c[2]), "+f"(c[3])
        : "r"(a[0]), "r"(a[1]), "r"(a[2]), "r"(a[3]), "r"(b0), "r"(b1));
}

// 128B-row tile, 8 granules of 16B, XOR-swizzled: any ldmatrix 8-lane phase
// covers all 32 banks.
__device__ __forceinline__ uint32_t tile_off(int row, int g) {
    return (uint32_t)(row * 128 + ((g ^ (row & 7)) * 16));
}

// ---------------------------------------------------------------------------
// Prep A: permute columns (xp[invp[c]] = x[c]) and convert fp32 -> fp16.
// PERM_R rows per CTA; invp cached in smem once per CTA.
// ---------------------------------------------------------------------------
__global__ __launch_bounds__(256)
void perm_conv_A_kernel(const float* __restrict__ x,
                        const int* __restrict__ invp) {
    __shared__ int   ip[K_DIM];
    __shared__ float rs[K_DIM];
    const int tid = threadIdx.x;
    for (int j = tid; j < K_DIM; j += 256) ip[j] = invp[j];
    __syncthreads();

    const int mbase = blockIdx.x * PERM_R;
    for (int r = 0; r < PERM_R; r++) {
        const float* xr = x + (size_t)(mbase + r) * K_DIM;
        for (int j = tid; j < K_DIM; j += 256)
            rs[ip[j]] = xr[j];                      // smem scatter
        __syncthreads();
        __half2* H = (__half2*)(g_A + (size_t)(mbase + r) * K_DIM);
        for (int j2 = tid; j2 < K_DIM / 2; j2 += 256)
            H[j2] = __floats2half2_rn(rs[2 * j2], rs[2 * j2 + 1]);
        __syncthreads();                            // rs reuse next row
    }
}

// Merged weight prep, float4-vectorized: exact fp16 int weights + outliers.
__global__ void prep_W_kernel(const float4* __restrict__ qw4,
                              const float4* __restrict__ fw4) {
    size_t idx = (size_t)blockIdx.x * 256 + threadIdx.x;   // over float4s
    const size_t nq4 = (size_t)N_DIM * KQ_DIM / 4;
    float4 v;
    __half2* dst;
    if (idx < nq4) { v = qw4[idx]; dst = (__half2*)(g_Q + 4 * idx); }
    else { v = fw4[idx - nq4]; dst = (__half2*)(g_FP + 4 * (idx - nq4)); }
    dst[0] = __floats2half2_rn(v.x, v.y);
    dst[1] = __floats2half2_rn(v.z, v.w);
}

// ---------------------------------------------------------------------------
// GEMM (exact R7 code): acc = xp[:, :3968]*q^T ; acc *= alpha[n] ;
// acc += outliers ; C = acc + bias.  Single fp16 MMA term throughout.
// CTA 256x128, 256 threads / 8 warps (4m x 2n), warp tile 64x64, KC=64,
// 4-stage cp.async pipeline.
// ---------------------------------------------------------------------------
__global__ __launch_bounds__(256, 1)
void gemm_hmma_kernel(const float* __restrict__ alpha,
                      const float* __restrict__ bias,
                      float* __restrict__ C) {
    extern __shared__ char smem[];
    const uint32_t sbase = smem_to_u32(smem);
    const int tid = threadIdx.x;
    const int wid = tid >> 5;
    const int lid = tid & 31;
    const int wm  = wid >> 1;          // 0..3 -> m offset wm*64
    const int wn  = wid & 1;           // 0..1 -> n offset wn*64
    const int m0  = blockIdx.y * TM;
    const int n0  = blockIdx.x * TN;

    float acc[4][8][4];                // [m16][n8][quad]
    #pragma unroll
    for (int i = 0; i < 4; i++)
        #pragma unroll
        for (int j = 0; j < 8; j++)
            #pragma unroll
            for (int t = 0; t < 4; t++) acc[i][j][t] = 0.0f;

    // ---- stage loader: 12 cp.async x 16B per thread ----
    const int lrow = tid >> 3;          // 0..31
    const int lg   = tid & 7;           // granule 0..7 within 128B row
    auto load_stage = [&](int slot, int kt) {
        const uint32_t stg = sbase + slot * STAGE_BYTES;
        const int k0 = kt * KC;
        #pragma unroll
        for (int p = 0; p < 8; p++) {   // A: 256 rows
            int row = lrow + p * 32;
            cpa16(stg + OFF_A + tile_off(row, lg),
                  g_A + (size_t)(m0 + row) * K_DIM + k0 + lg * 8);
        }
        if (kt < NQ_IT) {
            #pragma unroll
            for (int p = 0; p < 4; p++) {   // B: 128 rows, exact int weights
                int row = lrow + p * 32;
                cpa16(stg + OFF_B + tile_off(row, lg),
                      g_Q + (size_t)(n0 + row) * KQ_DIM + k0 + lg * 8);
            }
        } else {
            const int ko = k0 - KQ_DIM;     // 0 or 64
            #pragma unroll
            for (int p = 0; p < 4; p++) {   // B: fp outlier weights
                int row = lrow + p * 32;
                cpa16(stg + OFF_B + tile_off(row, lg),
                      g_FP + (size_t)(n0 + row) * N_OUTL + ko + lg * 8);
            }
        }
    };

    const int frow = lid & 15;
    const int fg   = lid >> 4;

    // per stage: 4 k16 s-steps; per s-step 8 LDSM + 32 independent MMAs
    auto compute_stage = [&](int slot) {
        const uint32_t stg = sbase + slot * STAGE_BYTES;
        #pragma unroll
        for (int s = 0; s < 4; s++) {
            const int g = 2 * s + fg;
            uint32_t a[4][4], b[4][4];
            #pragma unroll
            for (int j = 0; j < 4; j++) {
                int row = wn * 64 + j * 16 + frow;
                ldsm4(b[j], stg + OFF_B + tile_off(row, g));
            }
            #pragma unroll
            for (int i = 0; i < 4; i++) {
                int row = wm * 64 + i * 16 + frow;
                ldsm4(a[i], stg + OFF_A + tile_off(row, g));
            }
            #pragma unroll
            for (int i = 0; i < 4; i++)
                #pragma unroll
                for (int j = 0; j < 4; j++) {
                    mma16816(acc[i][2 * j],     a[i], b[j][0], b[j][2]);
                    mma16816(acc[i][2 * j + 1], a[i], b[j][1], b[j][3]);
                }
        }
    };

    const int tq = lid & 3;             // fragment col pair

    // ---- pipeline ----
    #pragma unroll
    for (int s = 0; s < STAGES - 1; s++) {
        load_stage(s, s);
        asm volatile("cp.async.commit_group;" ::: "memory");
    }
    for (int kt = 0; kt < NT; kt++) {
        asm volatile("cp.async.wait_group 2;" ::: "memory");
        __syncthreads();
        const int nx = kt + STAGES - 1;
        if (nx < NT) load_stage(nx & (STAGES - 1), nx);
        asm volatile("cp.async.commit_group;" ::: "memory");

        if (kt == NQ_IT) {
            // q-part complete: apply per-output-column alpha to accumulators
            #pragma unroll
            for (int j2 = 0; j2 < 8; j2++) {
                const int nc = n0 + wn * 64 + j2 * 8 + 2 * tq;
                const float s0 = alpha[nc], s1 = alpha[nc + 1];
                #pragma unroll
                for (int i = 0; i < 4; i++) {
                    acc[i][j2][0] *= s0; acc[i][j2][1] *= s1;
                    acc[i][j2][2] *= s0; acc[i][j2][3] *= s1;
                }
            }
        }
        compute_stage(kt & (STAGES - 1));
    }

    // ---- epilogue: bias + float2 stores ----
    const int qid = lid >> 2;
    #pragma unroll
    for (int i = 0; i < 4; i++) {
        const int mrow = m0 + wm * 64 + i * 16 + qid;
        #pragma unroll
        for (int j2 = 0; j2 < 8; j2++) {
            const int nc = n0 + wn * 64 + j2 * 8 + 2 * tq;
            const float b0 = bias[nc], b1 = bias[nc + 1];
            float2 v0 = make_float2(acc[i][j2][0] + b0, acc[i][j2][1] + b1);
            float2 v1 = make_float2(acc[i][j2][2] + b0, acc[i][j2][3] + b1);
            *(float2*)&C[(size_t)mrow * N_DIM + nc]       = v0;
            *(float2*)&C[(size_t)(mrow + 8) * N_DIM + nc] = v1;
        }
    }
}

// ---------------------------------------------------------------------------
// Launch. Inputs: input, q_weight, fp_weight, alpha_scale, bias, inv_col_perm.
// ---------------------------------------------------------------------------
extern "C" void kernel_launch(void* const* d_in, const int* in_sizes, int n_in,
                              void* d_out, int out_size) {
    const float* input = (const float*)d_in[0];
    const float* qw    = (const float*)d_in[1];
    const float* fw    = (const float*)d_in[2];
    const float* alpha = (const float*)d_in[3];
    const float* bias  = (const float*)d_in[4];
    const int*   invp  = (const int*)  d_in[5];
    float* out = (float*)d_out;

    perm_conv_A_kernel<<<M_ROWS / PERM_R, 256>>>(input, invp);
    prep_W_kernel<<<(N_DIM * K_DIM / 4) / 256, 256>>>((const float4*)qw,
                                                      (const float4*)fw);

    static bool attr_set = false;
    if (!attr_set) {
        cudaFuncSetAttribute(gemm_hmma_kernel,
                             cudaFuncAttributeMaxDynamicSharedMemorySize, SMEM_TOTAL);
        attr_set = true;
    }
    dim3 grid(N_DIM / TN, M_ROWS / TM);   // (32, 32)
    gemm_hmma_kernel<<<grid, 256, SMEM_TOTAL>>>(alpha, bias, out);
}

// round 11
// speedup vs baseline: 1.0986x; 1.0006x over previous
#include <cuda_runtime.h>
#include <cuda_fp16.h>
#include <cstdint>
#include <cstddef>

#define K_DIM  4096
#define M_ROWS 8192
#define N_DIM  4096
#define KQ_DIM 3968            // exact-fp16 integer-weight part
#define N_OUTL 128

// GEMM tiling
#define TM 256
#define TN 128
#define KC 64
#define NT (K_DIM / KC)        // 64 k-iterations
#define NQ_IT (KQ_DIM / KC)    // 62 q-part iterations
#define STAGES 4

// Stage smem layout (bytes): A 256x64 fp16 = 32K, B 128x64 fp16 = 16K
#define OFF_A 0
#define OFF_B (32 * 1024)
#define STAGE_BYTES (48 * 1024)
#define SMEM_TOTAL (STAGES * STAGE_BYTES)   // 196608

// ---------------------------------------------------------------------------
// Device-global scratch (no runtime allocation)
// ---------------------------------------------------------------------------
__device__ __half g_A [(size_t)M_ROWS * K_DIM];    // permuted x, fp16
__device__ __half g_Q [(size_t)N_DIM * KQ_DIM];    // exact fp16 int weights
__device__ __half g_FP[(size_t)N_DIM * N_OUTL];    // fp16 outlier weights
__device__ int    g_cp[K_DIM];                     // forward column perm

// ---------------------------------------------------------------------------
// Base-target PTX helpers
// ---------------------------------------------------------------------------
__device__ __forceinline__ uint32_t smem_to_u32(const void* p) {
    uint32_t a;
    asm("{ .reg .u64 t; cvta.to.shared.u64 t, %1; cvt.u32.u64 %0, t; }"
        : "=r"(a) : "l"(p));
    return a;
}

__device__ __forceinline__ void cpa16(uint32_t dst, const void* src) {
    asm volatile("cp.async.cg.shared.global [%0], [%1], 16;"
                 :: "r"(dst), "l"(src) : "memory");
}

__device__ __forceinline__ void ldsm4(uint32_t* r, uint32_t addr) {
    asm volatile("ldmatrix.sync.aligned.m8n8.x4.shared.b16 {%0,%1,%2,%3}, [%4];"
                 : "=r"(r[0]), "=r"(r[1]), "=r"(r[2]), "=r"(r[3]) : "r"(addr));
}

__device__ __forceinline__ void mma16816(float* c, const uint32_t* a,
                                         uint32_t b0, uint32_t b1) {
    asm volatile(
        "mma.sync.aligned.m16n8k16.row.col.f32.f16.f16.f32 "
        "{%0,%1,%2,%3}, {%4,%5,%6,%7}, {%8,%9}, {%0,%1,%2,%3};"
        : "+f"(c[0]), "+f"(c[1]), "+f"(c[2]), "+f"(c[3])
        : "r"(a[0]), "r"(a[1]), "r"(a[2]), "r"(a[3]), "r"(b0), "r"(b1));
}

// 128B-row tile, 8 granules of 16B, XOR-swizzled.
__device__ __forceinline__ uint32_t tile_off(int row, int g) {
    return (uint32_t)(row * 128 + ((g ^ (row & 7)) * 16));
}

// ---------------------------------------------------------------------------
// Prep A, pass 0: forward permutation cp[invp[c]] = c  (xp[j] = x[cp[j]]).
// ---------------------------------------------------------------------------
__global__ void build_cp_kernel(const int* __restrict__ invp) {
    int j = blockIdx.x * 256 + threadIdx.x;
    g_cp[invp[j]] = j;
}

// Prep A, pass 1: pure gather + fp16 convert. Coalesced writes, L2 gathers.
__global__ __launch_bounds__(256)
void perm_gather_A_kernel(const float* __restrict__ x) {
    size_t idx = (size_t)blockIdx.x * 256 + threadIdx.x;  // over M*K/2
    const int m  = (int)(idx >> 11);                      // K/2 = 2048
    const int j2 = (int)(idx & 2047);
    const float* xr = x + (size_t)m * K_DIM;
    const int c0 = g_cp[2 * j2], c1 = g_cp[2 * j2 + 1];
    ((__half2*)(g_A + (size_t)m * K_DIM))[j2] =
        __floats2half2_rn(xr[c0], xr[c1]);
}

// Merged weight prep, float4-vectorized.
__global__ void prep_W_kernel(const float4* __restrict__ qw4,
                              const float4* __restrict__ fw4) {
    size_t idx = (size_t)blockIdx.x * 256 + threadIdx.x;   // over float4s
    const size_t nq4 = (size_t)N_DIM * KQ_DIM / 4;
    float4 v;
    __half2* dst;
    if (idx < nq4) { v = qw4[idx]; dst = (__half2*)(g_Q + 4 * idx); }
    else { v = fw4[idx - nq4]; dst = (__half2*)(g_FP + 4 * (idx - nq4)); }
    dst[0] = __floats2half2_rn(v.x, v.y);
    dst[1] = __floats2half2_rn(v.z, v.w);
}

// ---------------------------------------------------------------------------
// GEMM: acc = xp[:, :3968]*q^T ; acc *= alpha[n] ; acc += outliers ; +bias.
// R7 structure (4-stage, single-buffered fragments) + address hoisting:
// walking global pointers in the loader, precomputed LDSM bases, one shared
// swizzle term per s-step.
// ---------------------------------------------------------------------------
__global__ __launch_bounds__(256, 1)
void gemm_hmma_kernel(const float* __restrict__ alpha,
                      const float* __restrict__ bias,
                      float* __restrict__ C) {
    extern __shared__ char smem[];
    const uint32_t sbase = smem_to_u32(smem);
    const int tid = threadIdx.x;
    const int wid = tid >> 5;
    const int lid = tid & 31;
    const int wm  = wid >> 1;
    const int wn  = wid & 1;
    const int m0  = blockIdx.y * TM;
    const int n0  = blockIdx.x * TN;

    float acc[4][8][4];
    #pragma unroll
    for (int i = 0; i < 4; i++)
        #pragma unroll
        for (int j = 0; j < 8; j++)
            #pragma unroll
            for (int t = 0; t < 4; t++) acc[i][j][t] = 0.0f;

    // ---- loader: walking pointers, constant per-row-group offsets ----
    const int lrow = tid >> 3;          // 0..31
    const int lg   = tid & 7;           // 16B granule within 128B row
    const __half* pA = g_A  + (size_t)(m0 + lrow) * K_DIM  + lg * 8;
    const __half* pQ = g_Q  + (size_t)(n0 + lrow) * KQ_DIM + lg * 8;
    const __half* pF = g_FP + (size_t)(n0 + lrow) * N_OUTL + lg * 8;
    const uint32_t dA = sbase + OFF_A + tile_off(lrow, lg);
    const uint32_t dB = sbase + OFF_B + tile_off(lrow, lg);

    // called with kt strictly increasing: 0..NT-1
    auto load_stage = [&](int slot, int kt) {
        const uint32_t so = (uint32_t)slot * STAGE_BYTES;
        #pragma unroll
        for (int p = 0; p < 8; p++)     // A: 256 rows (row-group stride 32)
            cpa16(dA + so + p * 4096u, pA + (size_t)p * (32 * K_DIM));
        pA += KC;
        if (kt < NQ_IT) {
            #pragma unroll
            for (int p = 0; p < 4; p++) // B: exact int weights
                cpa16(dB + so + p * 4096u, pQ + (size_t)p * (32 * KQ_DIM));
            pQ += KC;
        } else {
            const __half* f = pF + (size_t)(kt - NQ_IT) * KC;
            #pragma unroll
            for (int p = 0; p < 4; p++) // B: fp outlier weights
                cpa16(dB + so + p * 4096u, f + (size_t)p * (32 * N_OUTL));
        }
    };

    // ---- LDSM bases hoisted; row&7 identical across fragments ----
    const int frow = lid & 15;
    const int fg   = lid >> 4;
    const uint32_t r7 = (uint32_t)(frow & 7);
    uint32_t aoff[4], boff[4];
    #pragma unroll
    for (int i = 0; i < 4; i++)
        aoff[i] = sbase + OFF_A + (uint32_t)(wm * 64 + i * 16 + frow) * 128;
    #pragma unroll
    for (int j = 0; j < 4; j++)
        boff[j] = sbase + OFF_B + (uint32_t)(wn * 64 + j * 16 + frow) * 128;

    // per stage: 4 k16 s-steps; per s-step 8 LDSM + 32 independent MMAs
    auto compute_stage = [&](int slot) {
        const uint32_t so = (uint32_t)slot * STAGE_BYTES;
        #pragma unroll
        for (int s = 0; s < 4; s++) {
            const uint32_t sw = so + ((((uint32_t)(2 * s + fg)) ^ r7) << 4);
            uint32_t a[4][4], b[4][4];
            #pragma unroll
            for (int j = 0; j < 4; j++) ldsm4(b[j], boff[j] + sw);
            #pragma unroll
            for (int i = 0; i < 4; i++) ldsm4(a[i], aoff[i] + sw);
            #pragma unroll
            for (int i = 0; i < 4; i++)
                #pragma unroll
                for (int j = 0; j < 4; j++) {
                    mma16816(acc[i][2 * j],     a[i], b[j][0], b[j][2]);
                    mma16816(acc[i][2 * j + 1], a[i], b[j][1], b[j][3]);
                }
        }
    };

    const int tq = lid & 3;

    // ---- pipeline (R7 schedule) ----
    #pragma unroll
    for (int s = 0; s < STAGES - 1; s++) {
        load_stage(s, s);
        asm volatile("cp.async.commit_group;" ::: "memory");
    }
    for (int kt = 0; kt < NT; kt++) {
        asm volatile("cp.async.wait_group 2;" ::: "memory");
        __syncthreads();
        const int nx = kt + STAGES - 1;
        if (nx < NT) load_stage(nx & (STAGES - 1), nx);
        asm volatile("cp.async.commit_group;" ::: "memory");

        if (kt == NQ_IT) {
            // q-part complete: per-output-column alpha on accumulators
            #pragma unroll
            for (int j2 = 0; j2 < 8; j2++) {
                const int nc = n0 + wn * 64 + j2 * 8 + 2 * tq;
                const float s0 = alpha[nc], s1 = alpha[nc + 1];
                #pragma unroll
                for (int i = 0; i < 4; i++) {
                    acc[i][j2][0] *= s0; acc[i][j2][1] *= s1;
                    acc[i][j2][2] *= s0; acc[i][j2][3] *= s1;
                }
            }
        }
        compute_stage(kt & (STAGES - 1));
    }

    // ---- epilogue: bias + float2 stores ----
    const int qid = lid >> 2;
    #pragma unroll
    for (int i = 0; i < 4; i++) {
        const int mrow = m0 + wm * 64 + i * 16 + qid;
        #pragma unroll
        for (int j2 = 0; j2 < 8; j2++) {
            const int nc = n0 + wn * 64 + j2 * 8 + 2 * tq;
            const float b0 = bias[nc], b1 = bias[nc + 1];
            float2 v0 = make_float2(acc[i][j2][0] + b0, acc[i][j2][1] + b1);
            float2 v1 = make_float2(acc[i][j2][2] + b0, acc[i][j2][3] + b1);
            *(float2*)&C[(size_t)mrow * N_DIM + nc]       = v0;
            *(float2*)&C[(size_t)(mrow + 8) * N_DIM + nc] = v1;
        }
    }
}

// ---------------------------------------------------------------------------
// Launch. Inputs: input, q_weight, fp_weight, alpha_scale, bias, inv_col_perm.
// ---------------------------------------------------------------------------
extern "C" void kernel_launch(void* const* d_in, const int* in_sizes, int n_in,
                              void* d_out, int out_size) {
    const float* input = (const float*)d_in[0];
    const float* qw    = (const float*)d_in[1];
    const float* fw    = (const float*)d_in[2];
    const float* alpha = (const float*)d_in[3];
    const float* bias  = (const float*)d_in[4];
    const int*   invp  = (const int*)  d_in[5];
    float* out = (float*)d_out;

    build_cp_kernel<<<K_DIM / 256, 256>>>(invp);
    perm_gather_A_kernel<<<(M_ROWS * (K_DIM / 2)) / 256, 256>>>(input);
    prep_W_kernel<<<(N_DIM * K_DIM / 4) / 256, 256>>>((const float4*)qw,
                                                      (const float4*)fw);

    static bool attr_set = false;
    if (!attr_set) {
        cudaFuncSetAttribute(gemm_hmma_kernel,
                             cudaFuncAttributeMaxDynamicSharedMemorySize, SMEM_TOTAL);
        attr_set = true;
    }
    dim3 grid(N_DIM / TN, M_ROWS / TM);   // (32, 32)
    gemm_hmma_kernel<<<grid, 256, SMEM_TOTAL>>>(alpha, bias, out);
}

// round 12
// speedup vs baseline: 1.1419x; 1.0394x over previous
#include <cuda_runtime.h>
#include <cuda_fp16.h>
#include <cstdint>
#include <cstddef>

#define K_DIM  4096
#define M_ROWS 8192
#define N_DIM  4096
#define KQ_DIM 3968            // exact-fp16 integer-weight part
#define N_OUTL 128

// GEMM tiling: 128x128 CTA tile, 2 CTAs/SM
#define TM 128
#define TN 128
#define KC 64
#define NT (K_DIM / KC)        // 64 k-iterations
#define NQ_IT (KQ_DIM / KC)    // 62 q-part iterations
#define STAGES 3

// Stage smem layout (bytes): A 128x64 fp16 = 16K, B 128x64 fp16 = 16K
#define OFF_A 0
#define OFF_B (16 * 1024)
#define STAGE_BYTES (32 * 1024)
#define SMEM_TOTAL (STAGES * STAGE_BYTES)   // 98304 (2 CTAs -> 192K/SM)

// ---------------------------------------------------------------------------
// Device-global scratch (no runtime allocation)
// ---------------------------------------------------------------------------
__device__ __half g_A [(size_t)M_ROWS * K_DIM];    // permuted x, fp16
__device__ __half g_Q [(size_t)N_DIM * KQ_DIM];    // exact fp16 int weights
__device__ __half g_FP[(size_t)N_DIM * N_OUTL];    // fp16 outlier weights
__device__ int    g_cp[K_DIM];                     // forward column perm

// ---------------------------------------------------------------------------
// Base-target PTX helpers
// ---------------------------------------------------------------------------
__device__ __forceinline__ uint32_t smem_to_u32(const void* p) {
    uint32_t a;
    asm("{ .reg .u64 t; cvta.to.shared.u64 t, %1; cvt.u32.u64 %0, t; }"
        : "=r"(a) : "l"(p));
    return a;
}

__device__ __forceinline__ void cpa16(uint32_t dst, const void* src) {
    asm volatile("cp.async.cg.shared.global [%0], [%1], 16;"
                 :: "r"(dst), "l"(src) : "memory");
}

__device__ __forceinline__ void ldsm4(uint32_t* r, uint32_t addr) {
    asm volatile("ldmatrix.sync.aligned.m8n8.x4.shared.b16 {%0,%1,%2,%3}, [%4];"
                 : "=r"(r[0]), "=r"(r[1]), "=r"(r[2]), "=r"(r[3]) : "r"(addr));
}

__device__ __forceinline__ void mma16816(float* c, const uint32_t* a,
                                         uint32_t b0, uint32_t b1) {
    asm volatile(
        "mma.sync.aligned.m16n8k16.row.col.f32.f16.f16.f32 "
        "{%0,%1,%2,%3}, {%4,%5,%6,%7}, {%8,%9}, {%0,%1,%2,%3};"
        : "+f"(c[0]), "+f"(c[1]), "+f"(c[2]), "+f"(c[3])
        : "r"(a[0]), "r"(a[1]), "r"(a[2]), "r"(a[3]), "r"(b0), "r"(b1));
}

// 128B-row tile, 8 granules of 16B, XOR-swizzled (verified conflict-free).
__device__ __forceinline__ uint32_t tile_off(int row, int g) {
    return (uint32_t)(row * 128 + ((g ^ (row & 7)) * 16));
}

// ---------------------------------------------------------------------------
// Prep A, pass 0: forward permutation cp[invp[c]] = c  (xp[j] = x[cp[j]]).
// ---------------------------------------------------------------------------
__global__ void build_cp_kernel(const int* __restrict__ invp) {
    int j = blockIdx.x * 256 + threadIdx.x;
    g_cp[invp[j]] = j;
}

// Prep A, pass 1: pure gather + fp16 convert. Coalesced writes, L2 gathers.
__global__ __launch_bounds__(256)
void perm_gather_A_kernel(const float* __restrict__ x) {
    size_t idx = (size_t)blockIdx.x * 256 + threadIdx.x;  // over M*K/2
    const int m  = (int)(idx >> 11);                      // K/2 = 2048
    const int j2 = (int)(idx & 2047);
    const float* xr = x + (size_t)m * K_DIM;
    const int c0 = g_cp[2 * j2], c1 = g_cp[2 * j2 + 1];
    ((__half2*)(g_A + (size_t)m * K_DIM))[j2] =
        __floats2half2_rn(xr[c0], xr[c1]);
}

// Merged weight prep, float4-vectorized.
__global__ void prep_W_kernel(const float4* __restrict__ qw4,
                              const float4* __restrict__ fw4) {
    size_t idx = (size_t)blockIdx.x * 256 + threadIdx.x;   // over float4s
    const size_t nq4 = (size_t)N_DIM * KQ_DIM / 4;
    float4 v;
    __half2* dst;
    if (idx < nq4) { v = qw4[idx]; dst = (__half2*)(g_Q + 4 * idx); }
    else { v = fw4[idx - nq4]; dst = (__half2*)(g_FP + 4 * (idx - nq4)); }
    dst[0] = __floats2half2_rn(v.x, v.y);
    dst[1] = __floats2half2_rn(v.z, v.w);
}

// ---------------------------------------------------------------------------
// GEMM: acc = xp[:, :3968]*q^T ; acc *= alpha[n] ; acc += outliers ; +bias.
// CTA 128x128, 256 threads / 8 warps (2m x 4n), warp tile 64x32, KC=64,
// 3-stage cp.async pipeline, 2 CTAs per SM (independent barriers hide each
// other's sync/load bubbles).
// ---------------------------------------------------------------------------
__global__ __launch_bounds__(256, 2)
void gemm_hmma_kernel(const float* __restrict__ alpha,
                      const float* __restrict__ bias,
                      float* __restrict__ C) {
    extern __shared__ char smem[];
    const uint32_t sbase = smem_to_u32(smem);
    const int tid = threadIdx.x;
    const int wid = tid >> 5;
    const int lid = tid & 31;
    const int wm  = wid >> 2;          // 0..1 -> m offset wm*64
    const int wn  = wid & 3;           // 0..3 -> n offset wn*32
    const int m0  = blockIdx.y * TM;
    const int n0  = blockIdx.x * TN;

    float acc[4][4][4];                // [m16][n8][quad] = 64 regs
    #pragma unroll
    for (int i = 0; i < 4; i++)
        #pragma unroll
        for (int j = 0; j < 4; j++)
            #pragma unroll
            for (int t = 0; t < 4; t++) acc[i][j][t] = 0.0f;

    // ---- loader: 8 cp.async x 16B per thread ----
    const int lrow = tid >> 3;          // 0..31
    const int lg   = tid & 7;           // 16B granule within 128B row
    const __half* pA = g_A  + (size_t)(m0 + lrow) * K_DIM  + lg * 8;
    const __half* pQ = g_Q  + (size_t)(n0 + lrow) * KQ_DIM + lg * 8;
    const __half* pF = g_FP + (size_t)(n0 + lrow) * N_OUTL + lg * 8;
    const uint32_t dA = sbase + OFF_A + tile_off(lrow, lg);
    const uint32_t dB = sbase + OFF_B + tile_off(lrow, lg);

    auto load_stage = [&](int slot, int kt) {
        const uint32_t so = (uint32_t)slot * STAGE_BYTES;
        #pragma unroll
        for (int p = 0; p < 4; p++)     // A: 128 rows (row-group stride 32)
            cpa16(dA + so + p * 4096u, pA + (size_t)p * (32 * K_DIM));
        pA += KC;
        if (kt < NQ_IT) {
            #pragma unroll
            for (int p = 0; p < 4; p++) // B: exact int weights
                cpa16(dB + so + p * 4096u, pQ + (size_t)p * (32 * KQ_DIM));
            pQ += KC;
        } else {
            const __half* f = pF + (size_t)(kt - NQ_IT) * KC;
            #pragma unroll
            for (int p = 0; p < 4; p++) // B: fp outlier weights
                cpa16(dB + so + p * 4096u, f + (size_t)p * (32 * N_OUTL));
        }
    };

    // ---- fragment addressing ----
    const int frow = lid & 15;
    const int fg   = lid >> 4;
    const uint32_t r7 = (uint32_t)(frow & 7);
    uint32_t aoff[4], boff[2];
    #pragma unroll
    for (int i = 0; i < 4; i++)
        aoff[i] = sbase + OFF_A + (uint32_t)(wm * 64 + i * 16 + frow) * 128;
    #pragma unroll
    for (int j = 0; j < 2; j++)
        boff[j] = sbase + OFF_B + (uint32_t)(wn * 32 + j * 16 + frow) * 128;

    // per stage: 4 k16 s-steps; per s-step 6 LDSM + 16 independent MMAs
    auto compute_stage = [&](int slot) {
        const uint32_t so = (uint32_t)slot * STAGE_BYTES;
        #pragma unroll
        for (int s = 0; s < 4; s++) {
            const uint32_t sw = so + ((((uint32_t)(2 * s + fg)) ^ r7) << 4);
            uint32_t a[4][4], b[2][4];
            #pragma unroll
            for (int j = 0; j < 2; j++) ldsm4(b[j], boff[j] + sw);
            #pragma unroll
            for (int i = 0; i < 4; i++) ldsm4(a[i], aoff[i] + sw);
            #pragma unroll
            for (int i = 0; i < 4; i++)
                #pragma unroll
                for (int j = 0; j < 2; j++) {
                    mma16816(acc[i][2 * j],     a[i], b[j][0], b[j][2]);
                    mma16816(acc[i][2 * j + 1], a[i], b[j][1], b[j][3]);
                }
        }
    };

    const int tq = lid & 3;

    // ---- pipeline: 3 stages, wait_group 1 ----
    #pragma unroll
    for (int s = 0; s < STAGES - 1; s++) {
        load_stage(s, s);
        asm volatile("cp.async.commit_group;" ::: "memory");
    }
    int slot = 0;
    for (int kt = 0; kt < NT; kt++) {
        asm volatile("cp.async.wait_group 1;" ::: "memory");
        __syncthreads();
        const int nx = kt + STAGES - 1;
        if (nx < NT) {
            int ns = slot + 2; if (ns >= STAGES) ns -= STAGES;
            load_stage(ns, nx);
        }
        asm volatile("cp.async.commit_group;" ::: "memory");

        if (kt == NQ_IT) {
            // q-part complete: per-output-column alpha on accumulators
            #pragma unroll
            for (int j2 = 0; j2 < 4; j2++) {
                const int nc = n0 + wn * 32 + j2 * 8 + 2 * tq;
                const float s0 = alpha[nc], s1 = alpha[nc + 1];
                #pragma unroll
                for (int i = 0; i < 4; i++) {
                    acc[i][j2][0] *= s0; acc[i][j2][1] *= s1;
                    acc[i][j2][2] *= s0; acc[i][j2][3] *= s1;
                }
            }
        }
        compute_stage(slot);
        slot++; if (slot == STAGES) slot = 0;
    }

    // ---- epilogue: bias + float2 stores ----
    const int qid = lid >> 2;
    #pragma unroll
    for (int i = 0; i < 4; i++) {
        const int mrow = m0 + wm * 64 + i * 16 + qid;
        #pragma unroll
        for (int j2 = 0; j2 < 4; j2++) {
            const int nc = n0 + wn * 32 + j2 * 8 + 2 * tq;
            const float b0 = bias[nc], b1 = bias[nc + 1];
            float2 v0 = make_float2(acc[i][j2][0] + b0, acc[i][j2][1] + b1);
            float2 v1 = make_float2(acc[i][j2][2] + b0, acc[i][j2][3] + b1);
            *(float2*)&C[(size_t)mrow * N_DIM + nc]       = v0;
            *(float2*)&C[(size_t)(mrow + 8) * N_DIM + nc] = v1;
        }
    }
}

// ---------------------------------------------------------------------------
// Launch. Inputs: input, q_weight, fp_weight, alpha_scale, bias, inv_col_perm.
// ---------------------------------------------------------------------------
extern "C" void kernel_launch(void* const* d_in, const int* in_sizes, int n_in,
                              void* d_out, int out_size) {
    const float* input = (const float*)d_in[0];
    const float* qw    = (const float*)d_in[1];
    const float* fw    = (const float*)d_in[2];
    const float* alpha = (const float*)d_in[3];
    const float* bias  = (const float*)d_in[4];
    const int*   invp  = (const int*)  d_in[5];
    float* out = (float*)d_out;

    build_cp_kernel<<<K_DIM / 256, 256>>>(invp);
    perm_gather_A_kernel<<<(M_ROWS * (K_DIM / 2)) / 256, 256>>>(input);
    prep_W_kernel<<<(N_DIM * K_DIM / 4) / 256, 256>>>((const float4*)qw,
                                                      (const float4*)fw);

    static bool attr_set = false;
    if (!attr_set) {
        cudaFuncSetAttribute(gemm_hmma_kernel,
                             cudaFuncAttributeMaxDynamicSharedMemorySize, SMEM_TOTAL);
        attr_set = true;
    }
    dim3 grid(N_DIM / TN, M_ROWS / TM);   // (32, 64) = 2048 CTAs
    gemm_hmma_kernel<<<grid, 256, SMEM_TOTAL>>>(alpha, bias, out);
}

// round 13
// speedup vs baseline: 1.1768x; 1.0306x over previous
#include <cuda_runtime.h>
#include <cuda_fp16.h>
#include <cstdint>
#include <cstddef>

#define K_DIM  4096
#define M_ROWS 8192
#define N_DIM  4096
#define KQ_DIM 3968            // exact-fp16 integer-weight part
#define N_OUTL 128

// GEMM tiling: 128x128 CTA tile, 2 CTAs/SM
#define TM 128
#define TN 128
#define KC 64
#define NT (K_DIM / KC)        // 64 k-iterations
#define NQ_IT (KQ_DIM / KC)    // 62 q-part iterations
#define STAGES 3

// Stage smem layout (bytes): A 128x64 fp16 = 16K, B 128x64 fp16 = 16K
#define OFF_A 0
#define OFF_B (16 * 1024)
#define STAGE_BYTES (32 * 1024)
#define SMEM_TOTAL (STAGES * STAGE_BYTES)   // 98304 (2 CTAs -> 192K/SM)

// fused prep kernel split point
#define GATHER_BLOCKS (M_ROWS * (K_DIM / 2) / 256)     // 65536
#define W_BLOCKS      ((N_DIM * K_DIM / 4) / 256)      // 16384

// ---------------------------------------------------------------------------
// Device-global scratch (no runtime allocation)
// ---------------------------------------------------------------------------
__device__ __half g_A [(size_t)M_ROWS * K_DIM];    // permuted x, fp16
__device__ __half g_Q [(size_t)N_DIM * KQ_DIM];    // exact fp16 int weights
__device__ __half g_FP[(size_t)N_DIM * N_OUTL];    // fp16 outlier weights
__device__ int    g_cp[K_DIM];                     // forward column perm

// ---------------------------------------------------------------------------
// Base-target PTX helpers
// ---------------------------------------------------------------------------
__device__ __forceinline__ uint32_t smem_to_u32(const void* p) {
    uint32_t a;
    asm("{ .reg .u64 t; cvta.to.shared.u64 t, %1; cvt.u32.u64 %0, t; }"
        : "=r"(a) : "l"(p));
    return a;
}

__device__ __forceinline__ void cpa16(uint32_t dst, const void* src) {
    asm volatile("cp.async.cg.shared.global [%0], [%1], 16;"
                 :: "r"(dst), "l"(src) : "memory");
}

__device__ __forceinline__ void ldsm4(uint32_t* r, uint32_t addr) {
    asm volatile("ldmatrix.sync.aligned.m8n8.x4.shared.b16 {%0,%1,%2,%3}, [%4];"
                 : "=r"(r[0]), "=r"(r[1]), "=r"(r[2]), "=r"(r[3]) : "r"(addr));
}

__device__ __forceinline__ void mma16816(float* c, const uint32_t* a,
                                         uint32_t b0, uint32_t b1) {
    asm volatile(
        "mma.sync.aligned.m16n8k16.row.col.f32.f16.f16.f32 "
        "{%0,%1,%2,%3}, {%4,%5,%6,%7}, {%8,%9}, {%0,%1,%2,%3};"
        : "+f"(c[0]), "+f"(c[1]), "+f"(c[2]), "+f"(c[3])
        : "r"(a[0]), "r"(a[1]), "r"(a[2]), "r"(a[3]), "r"(b0), "r"(b1));
}

// 128B-row tile, 8 granules of 16B, XOR-swizzled (verified conflict-free).
__device__ __forceinline__ uint32_t tile_off(int row, int g) {
    return (uint32_t)(row * 128 + ((g ^ (row & 7)) * 16));
}

// ---------------------------------------------------------------------------
// Prep pass 0: forward permutation cp[invp[c]] = c  (xp[j] = x[cp[j]]).
// ---------------------------------------------------------------------------
__global__ void build_cp_kernel(const int* __restrict__ invp) {
    int j = blockIdx.x * 256 + threadIdx.x;
    g_cp[invp[j]] = j;
}

// Prep pass 1 (fused): A-gather+convert blocks, then W-convert blocks.
__global__ __launch_bounds__(256)
void prep_AW_kernel(const float* __restrict__ x,
                    const float4* __restrict__ qw4,
                    const float4* __restrict__ fw4) {
    const int b = blockIdx.x;
    if (b < GATHER_BLOCKS) {
        size_t idx = (size_t)b * 256 + threadIdx.x;        // over M*K/2
        const int m  = (int)(idx >> 11);                   // K/2 = 2048
        const int j2 = (int)(idx & 2047);
        const float* xr = x + (size_t)m * K_DIM;
        const int c0 = g_cp[2 * j2], c1 = g_cp[2 * j2 + 1];
        ((__half2*)(g_A + (size_t)m * K_DIM))[j2] =
            __floats2half2_rn(xr[c0], xr[c1]);
    } else {
        size_t idx = (size_t)(b - GATHER_BLOCKS) * 256 + threadIdx.x;
        const size_t nq4 = (size_t)N_DIM * KQ_DIM / 4;
        float4 v;
        __half2* dst;
        if (idx < nq4) { v = qw4[idx]; dst = (__half2*)(g_Q + 4 * idx); }
        else { v = fw4[idx - nq4]; dst = (__half2*)(g_FP + 4 * (idx - nq4)); }
        dst[0] = __floats2half2_rn(v.x, v.y);
        dst[1] = __floats2half2_rn(v.z, v.w);
    }
}

// ---------------------------------------------------------------------------
// GEMM: acc = xp[:, :3968]*q^T ; acc *= alpha[n] ; acc += outliers ; +bias.
// CTA 128x128, 256 threads / 8 warps (2m x 4n), warp tile 64x32, KC=64,
// 3-stage cp.async pipeline, 2 CTAs/SM. Loop split so the 60-iteration hot
// loop is one straight-line basic block (no loader branch, no alpha branch).
// ---------------------------------------------------------------------------
__global__ __launch_bounds__(256, 2)
void gemm_hmma_kernel(const float* __restrict__ alpha,
                      const float* __restrict__ bias,
                      float* __restrict__ C) {
    extern __shared__ char smem[];
    const uint32_t sbase = smem_to_u32(smem);
    const int tid = threadIdx.x;
    const int wid = tid >> 5;
    const int lid = tid & 31;
    const int wm  = wid >> 2;          // 0..1 -> m offset wm*64
    const int wn  = wid & 3;           // 0..3 -> n offset wn*32
    const int m0  = blockIdx.y * TM;
    const int n0  = blockIdx.x * TN;

    float acc[4][4][4];                // [m16][n8][quad] = 64 regs
    #pragma unroll
    for (int i = 0; i < 4; i++)
        #pragma unroll
        for (int j = 0; j < 4; j++)
            #pragma unroll
            for (int t = 0; t < 4; t++) acc[i][j][t] = 0.0f;

    // ---- loader: walking pointers, 8 cp.async x 16B per thread ----
    const int lrow = tid >> 3;          // 0..31
    const int lg   = tid & 7;           // 16B granule within 128B row
    const __half* pA = g_A  + (size_t)(m0 + lrow) * K_DIM  + lg * 8;
    const __half* pQ = g_Q  + (size_t)(n0 + lrow) * KQ_DIM + lg * 8;
    const __half* pF = g_FP + (size_t)(n0 + lrow) * N_OUTL + lg * 8;
    const uint32_t dA = sbase + OFF_A + tile_off(lrow, lg);
    const uint32_t dB = sbase + OFF_B + tile_off(lrow, lg);

    auto load_q = [&](uint32_t so) {    // straight-line, no branches
        #pragma unroll
        for (int p = 0; p < 4; p++)
            cpa16(dA + so + p * 4096u, pA + (size_t)p * (32 * K_DIM));
        #pragma unroll
        for (int p = 0; p < 4; p++)
            cpa16(dB + so + p * 4096u, pQ + (size_t)p * (32 * KQ_DIM));
        pA += KC; pQ += KC;
    };
    auto load_fp = [&](uint32_t so, int t) {
        const __half* f = pF + t * KC;
        #pragma unroll
        for (int p = 0; p < 4; p++)
            cpa16(dA + so + p * 4096u, pA + (size_t)p * (32 * K_DIM));
        #pragma unroll
        for (int p = 0; p < 4; p++)
            cpa16(dB + so + p * 4096u, f + (size_t)p * (32 * N_OUTL));
        pA += KC;
    };

    // ---- fragment addressing ----
    const int frow = lid & 15;
    const int fg   = lid >> 4;
    const uint32_t r7 = (uint32_t)(frow & 7);
    uint32_t aoff[4], boff[2];
    #pragma unroll
    for (int i = 0; i < 4; i++)
        aoff[i] = sbase + OFF_A + (uint32_t)(wm * 64 + i * 16 + frow) * 128;
    #pragma unroll
    for (int j = 0; j < 2; j++)
        boff[j] = sbase + OFF_B + (uint32_t)(wn * 32 + j * 16 + frow) * 128;

    auto compute_stage = [&](uint32_t so) {
        #pragma unroll
        for (int s = 0; s < 4; s++) {
            const uint32_t sw = so + ((((uint32_t)(2 * s + fg)) ^ r7) << 4);
            uint32_t a[4][4], b[2][4];
            #pragma unroll
            for (int j = 0; j < 2; j++) ldsm4(b[j], boff[j] + sw);
            #pragma unroll
            for (int i = 0; i < 4; i++) ldsm4(a[i], aoff[i] + sw);
            #pragma unroll
            for (int i = 0; i < 4; i++)
                #pragma unroll
                for (int j = 0; j < 2; j++) {
                    mma16816(acc[i][2 * j],     a[i], b[j][0], b[j][2]);
                    mma16816(acc[i][2 * j + 1], a[i], b[j][1], b[j][3]);
                }
        }
    };

    auto adv = [](uint32_t& o) {
        o += STAGE_BYTES;
        if (o == SMEM_TOTAL) o = 0;
    };
    const int tq = lid & 3;

    // ---- prologue: stages for tiles 0,1 (both Q) ----
    load_q(0);
    asm volatile("cp.async.commit_group;" ::: "memory");
    load_q(STAGE_BYTES);
    asm volatile("cp.async.commit_group;" ::: "memory");
    uint32_t cur = 0, nxt = 2 * STAGE_BYTES;

    // ---- hot loop: 60 iters, prefetch tiles 2..61 (all Q), one basic block
    for (int kt = 0; kt < NQ_IT - 2; kt++) {
        asm volatile("cp.async.wait_group 1;" ::: "memory");
        __syncthreads();
        load_q(nxt);
        asm volatile("cp.async.commit_group;" ::: "memory");
        compute_stage(cur);
        adv(cur); adv(nxt);
    }

    // ---- transition: 2 iters, prefetch FP tiles 62,63 ----
    #pragma unroll
    for (int t = 0; t < 2; t++) {
        asm volatile("cp.async.wait_group 1;" ::: "memory");
        __syncthreads();
        load_fp(nxt, t);
        asm volatile("cp.async.commit_group;" ::: "memory");
        compute_stage(cur);
        adv(cur); adv(nxt);
    }

    // ---- q-part complete: per-output-column alpha on accumulators ----
    #pragma unroll
    for (int j2 = 0; j2 < 4; j2++) {
        const int nc = n0 + wn * 32 + j2 * 8 + 2 * tq;
        const float s0 = alpha[nc], s1 = alpha[nc + 1];
        #pragma unroll
        for (int i = 0; i < 4; i++) {
            acc[i][j2][0] *= s0; acc[i][j2][1] *= s1;
            acc[i][j2][2] *= s0; acc[i][j2][3] *= s1;
        }
    }

    // ---- tail: tiles 62,63 (no further loads, no commits) ----
    asm volatile("cp.async.wait_group 1;" ::: "memory");
    __syncthreads();
    compute_stage(cur);
    adv(cur);
    asm volatile("cp.async.wait_group 0;" ::: "memory");
    __syncthreads();
    compute_stage(cur);

    // ---- epilogue: bias + float2 stores ----
    const int qid = lid >> 2;
    #pragma unroll
    for (int i = 0; i < 4; i++) {
        const int mrow = m0 + wm * 64 + i * 16 + qid;
        #pragma unroll
        for (int j2 = 0; j2 < 4; j2++) {
            const int nc = n0 + wn * 32 + j2 * 8 + 2 * tq;
            const float b0 = bias[nc], b1 = bias[nc + 1];
            float2 v0 = make_float2(acc[i][j2][0] + b0, acc[i][j2][1] + b1);
            float2 v1 = make_float2(acc[i][j2][2] + b0, acc[i][j2][3] + b1);
            *(float2*)&C[(size_t)mrow * N_DIM + nc]       = v0;
            *(float2*)&C[(size_t)(mrow + 8) * N_DIM + nc] = v1;
        }
    }
}

// ---------------------------------------------------------------------------
// Launch. Inputs: input, q_weight, fp_weight, alpha_scale, bias, inv_col_perm.
// ---------------------------------------------------------------------------
extern "C" void kernel_launch(void* const* d_in, const int* in_sizes, int n_in,
                              void* d_out, int out_size) {
    const float* input = (const float*)d_in[0];
    const float* qw    = (const float*)d_in[1];
    const float* fw    = (const float*)d_in[2];
    const float* alpha = (const float*)d_in[3];
    const float* bias  = (const float*)d_in[4];
    const int*   invp  = (const int*)  d_in[5];
    float* out = (float*)d_out;

    build_cp_kernel<<<K_DIM / 256, 256>>>(invp);
    prep_AW_kernel<<<GATHER_BLOCKS + W_BLOCKS, 256>>>(
        input, (const float4*)qw, (const float4*)fw);

    static bool attr_set = false;
    if (!attr_set) {
        cudaFuncSetAttribute(gemm_hmma_kernel,
                             cudaFuncAttributeMaxDynamicSharedMemorySize, SMEM_TOTAL);
        attr_set = true;
    }
    dim3 grid(N_DIM / TN, M_ROWS / TM);   // (32, 64) = 2048 CTAs
    gemm_hmma_kernel<<<grid, 256, SMEM_TOTAL>>>(alpha, bias, out);
}